// round 3
// baseline (speedup 1.0000x reference)
#include <cuda_runtime.h>

// YOLO v0 loss, fused single launch, coalesced-load version.
//
// Round-2 finding: per-thread 80B groups made each warp LDG.128 touch 20
// cache lines (lane stride 80B) -> ~200 L1tex wavefronts per warp-iter,
// which at ~1 wf/cyc/SM accounted for ~80% of runtime. Fix: warp loads
// 2560B per tensor with 5 fully-coalesced LDG.128 (4 lines each), stages
// through shared memory (bank-conflict-free both directions), then lanes
// read their 4-cell (80B) groups back via LDS.128.

#define LAMBDA_COOR  5.0f
#define LAMBDA_NOOBJ 0.5f

static const int TOTAL_CELLS = 128 * 256 * 256;   // 8,388,608
static const int BLOCK       = 256;               // 8 warps
static const int WARPS       = BLOCK / 32;
static const int CELLS_PER_WARP  = 128;           // 4 cells/lane
static const int F4_PER_WARP     = CELLS_PER_WARP * 5 / 4;   // 160 float4 = 2560 B
static const int CELLS_PER_BLOCK = WARPS * CELLS_PER_WARP;   // 1024
static const int GRID        = TOTAL_CELLS / CELLS_PER_BLOCK; // 8192 exactly

__device__ float        g_partials[GRID];
__device__ unsigned int g_done_count = 0;

__device__ __forceinline__ float cell_loss(float o0, float o1, float o2, float o3, float o4,
                                           float t0, float t1, float t2, float t3, float t4) {
    float d1 = o1 - t1;
    float d2 = o2 - t2;
    float d3 = o3 - t3;
    float d4 = o4 - t4;
    float sq = fmaf(d1, d1, fmaf(d2, d2, fmaf(d3, d3, d4 * d4)));
    float e  = o0 - 1.0f;
    float obj   = fmaf(LAMBDA_COOR, sq, e * e);
    float noobj = LAMBDA_NOOBJ * o0 * o0;
    return (t0 > 0.0f) ? obj : noobj;
}

__device__ __forceinline__ float block_reduce(float acc, float* s_warp) {
#pragma unroll
    for (int off = 16; off > 0; off >>= 1)
        acc += __shfl_down_sync(0xFFFFFFFFu, acc, off);
    int lane = threadIdx.x & 31;
    int wid  = threadIdx.x >> 5;
    if (lane == 0) s_warp[wid] = acc;
    __syncthreads();
    float v = 0.0f;
    if (wid == 0) {
        v = (lane < WARPS) ? s_warp[lane] : 0.0f;
#pragma unroll
        for (int off = 4; off > 0; off >>= 1)
            v += __shfl_down_sync(0xFFFFFFFFu, v, off);
    }
    return v;   // valid in thread 0 only
}

__global__ __launch_bounds__(BLOCK)
void yolo_loss_fused(const float* __restrict__ out, const float* __restrict__ tgt,
                     float* __restrict__ d_loss) {
    // Per-warp staging: [tensor][warp][160 float4]  (40 KB/block)
    __shared__ float4 s_stage[2][WARPS][F4_PER_WARP];
    __shared__ float  s_warp[WARPS];
    __shared__ bool   s_is_last;

    const int lane = threadIdx.x & 31;
    const int wid  = threadIdx.x >> 5;

    // Warp's float4 window in the flat tensors.
    const size_t wbase = ((size_t)blockIdx.x * WARPS + wid) * F4_PER_WARP;
    const float4* o4 = reinterpret_cast<const float4*>(out) + wbase;
    const float4* t4 = reinterpret_cast<const float4*>(tgt) + wbase;

    // Coalesced streaming loads: LDG j covers bytes [j*512, j*512+512),
    // lane stride 16B -> 4 lines per LDG.
#pragma unroll
    for (int j = 0; j < 5; j++)
        s_stage[0][wid][j * 32 + lane] = __ldcs(o4 + j * 32 + lane);
#pragma unroll
    for (int j = 0; j < 5; j++)
        s_stage[1][wid][j * 32 + lane] = __ldcs(t4 + j * 32 + lane);

    __syncwarp();

    // Each lane reads its 4-cell group: 5 float4 at float4-stride 5
    // (byte stride 80 -> conflict-free LDS.128 per quarter-warp phase).
    float4 a0 = s_stage[0][wid][lane * 5 + 0];
    float4 a1 = s_stage[0][wid][lane * 5 + 1];
    float4 a2 = s_stage[0][wid][lane * 5 + 2];
    float4 a3 = s_stage[0][wid][lane * 5 + 3];
    float4 a4 = s_stage[0][wid][lane * 5 + 4];
    float4 b0 = s_stage[1][wid][lane * 5 + 0];
    float4 b1 = s_stage[1][wid][lane * 5 + 1];
    float4 b2 = s_stage[1][wid][lane * 5 + 2];
    float4 b3 = s_stage[1][wid][lane * 5 + 3];
    float4 b4 = s_stage[1][wid][lane * 5 + 4];

    // 4 cells per lane across the 5 float4s.
    float acc;
    acc  = cell_loss(a0.x, a0.y, a0.z, a0.w, a1.x,  b0.x, b0.y, b0.z, b0.w, b1.x);
    acc += cell_loss(a1.y, a1.z, a1.w, a2.x, a2.y,  b1.y, b1.z, b1.w, b2.x, b2.y);
    acc += cell_loss(a2.z, a2.w, a3.x, a3.y, a3.z,  b2.z, b2.w, b3.x, b3.y, b3.z);
    acc += cell_loss(a3.w, a4.x, a4.y, a4.z, a4.w,  b3.w, b4.x, b4.y, b4.z, b4.w);

    float bsum = block_reduce(acc, s_warp);

    if (threadIdx.x == 0) {
        g_partials[blockIdx.x] = bsum;
        __threadfence();
        unsigned int n = atomicAdd(&g_done_count, 1u);
        s_is_last = (n == (unsigned int)(GRID - 1));
    }
    __syncthreads();

    if (s_is_last) {
        float t = 0.0f;
#pragma unroll
        for (int i = threadIdx.x; i < GRID; i += BLOCK)
            t += g_partials[i];
        float total = block_reduce(t, s_warp);
        if (threadIdx.x == 0) {
            d_loss[0] = total * (1.0f / 128.0f);
            g_done_count = 0;                  // reset for next graph replay
        }
    }
}

extern "C" void kernel_launch(void* const* d_in, const int* in_sizes, int n_in,
                              void* d_out, int out_size) {
    const float* outputs = (const float*)d_in[0];
    const float* targets = (const float*)d_in[1];
    float* loss = (float*)d_out;

    yolo_loss_fused<<<GRID, BLOCK>>>(outputs, targets, loss);
}

// round 4
// speedup vs baseline: 1.1366x; 1.1366x over previous
#include <cuda_runtime.h>

// YOLO v0 loss — fused single launch, fully-coalesced channel-oblivious version.
//
// R2 (thread owns 4 contiguous cells, 80B stride): 200 L1tex wavefronts per
// warp-iter -> bound at 5.7TB/s. R3 (smem staging): worse (L1 datapath x3,
// occupancy drop). R4: coalesced float4 loads, per-element channel derived
// from index algebra; per-cell obj mask comes from (a) the lane's own float4
// (second cell) or (b) one L1-hit scalar LDG per j (first cell).
//
// Warp chunk = 640 floats (128 cells), divisible by 5, so
//   channel(e) = (128j + 4L + k) mod 5   with 128 mod 5 == 3.

#define LAMBDA_COOR  5.0f
#define LAMBDA_NOOBJ 0.5f

static const int TOTAL_CELLS  = 128 * 256 * 256;        // 8,388,608
static const int BLOCK        = 256;                    // 8 warps
static const int WARPS        = BLOCK / 32;
static const int FLOATS_PER_WARP = 640;                 // 128 cells
static const int CELLS_PER_BLOCK = WARPS * 128;         // 1024
static const int GRID         = TOTAL_CELLS / CELLS_PER_BLOCK;  // 8192

__device__ float        g_partials[GRID];
__device__ unsigned int g_done_count = 0;

__device__ __forceinline__ float block_reduce(float acc, float* s_warp) {
#pragma unroll
    for (int off = 16; off > 0; off >>= 1)
        acc += __shfl_down_sync(0xFFFFFFFFu, acc, off);
    int lane = threadIdx.x & 31;
    int wid  = threadIdx.x >> 5;
    if (lane == 0) s_warp[wid] = acc;
    __syncthreads();
    float v = 0.0f;
    if (wid == 0) {
        v = (lane < WARPS) ? s_warp[lane] : 0.0f;
#pragma unroll
        for (int off = 4; off > 0; off >>= 1)
            v += __shfl_down_sync(0xFFFFFFFFu, v, off);
    }
    return v;   // valid in thread 0 only
}

__global__ __launch_bounds__(BLOCK)
void yolo_loss_fused(const float* __restrict__ out, const float* __restrict__ tgt,
                     float* __restrict__ d_loss) {
    const int lane = threadIdx.x & 31;
    const int wid  = threadIdx.x >> 5;

    const size_t warp_gid = (size_t)blockIdx.x * WARPS + wid;
    const size_t base_f   = warp_gid * FLOATS_PER_WARP;          // divisible by 5

    const float4* o4 = reinterpret_cast<const float4*>(out) + base_f / 4;
    const float4* t4 = reinterpret_cast<const float4*>(tgt) + base_f / 4;

    // ---- Fully coalesced loads: lane stride 16B, each LDG.128 = 4 lines ----
    float4 ao[5], at[5];
#pragma unroll
    for (int j = 0; j < 5; j++)
        ao[j] = __ldcs(o4 + j * 32 + lane);   // streaming: touched once
#pragma unroll
    for (int j = 0; j < 5; j++)
        at[j] = t4[j * 32 + lane];            // default: mask re-reads hit L1

    // Channel phase of this lane: (4L) mod 5; per-j offset (128j) mod 5 = 3j mod 5.
    const int r4 = (4 * lane) % 5;
    const int joff[5] = {0, 3, 1, 4, 2};      // (3j) mod 5

    // First-cell conf mask per j: one scalar L1-hit load each (line just fetched).
    float conf0[5];
    int   c0v[5];
#pragma unroll
    for (int j = 0; j < 5; j++) {
        int c0 = r4 + joff[j];
        if (c0 >= 5) c0 -= 5;
        c0v[j] = c0;
        size_t f0 = base_f + (size_t)(128 * j + 4 * lane - c0);   // conf index of first cell
        conf0[j] = __ldg(tgt + f0);
    }

    float acc = 0.0f;
#pragma unroll
    for (int j = 0; j < 5; j++) {
        const int c0 = c0v[j];
        const bool m0 = conf0[j] > 0.0f;

        // Second cell's conf (cell f0+5) lives in this lane's own float4 at
        // component k = 5 - c0 (only when c0 >= 2; otherwise unused).
        float tm1 = (c0 == 2) ? at[j].w : (c0 == 3) ? at[j].z : at[j].y;
        const bool m1 = tm1 > 0.0f;

        const float fo[4] = {ao[j].x, ao[j].y, ao[j].z, ao[j].w};
        const float ft[4] = {at[j].x, at[j].y, at[j].z, at[j].w};

#pragma unroll
        for (int k = 0; k < 4; k++) {
            int  ck = c0 + k;
            bool hi = ck >= 5;
            if (hi) ck -= 5;
            bool m  = hi ? m1 : m0;

            float o = fo[k], t = ft[k];
            float d = o - t;
            float coord = m ? LAMBDA_COOR * d * d : 0.0f;       // coord channels
            float e1 = o - 1.0f;
            float confc = m ? e1 * e1 : LAMBDA_NOOBJ * o * o;   // conf channel
            acc += (ck == 0) ? confc : coord;
        }
    }

    __shared__ float s_warp[WARPS];
    __shared__ bool  s_is_last;
    float bsum = block_reduce(acc, s_warp);

    if (threadIdx.x == 0) {
        g_partials[blockIdx.x] = bsum;
        __threadfence();
        unsigned int n = atomicAdd(&g_done_count, 1u);
        s_is_last = (n == (unsigned int)(GRID - 1));
    }
    __syncthreads();

    if (s_is_last) {
        float t = 0.0f;
#pragma unroll
        for (int i = threadIdx.x; i < GRID; i += BLOCK)
            t += g_partials[i];
        float total = block_reduce(t, s_warp);
        if (threadIdx.x == 0) {
            d_loss[0] = total * (1.0f / 128.0f);
            g_done_count = 0;                 // reset for next graph replay
        }
    }
}

extern "C" void kernel_launch(void* const* d_in, const int* in_sizes, int n_in,
                              void* d_out, int out_size) {
    const float* outputs = (const float*)d_in[0];
    const float* targets = (const float*)d_in[1];
    float* loss = (float*)d_out;

    yolo_loss_fused<<<GRID, BLOCK>>>(outputs, targets, loss);
}

// round 5
// speedup vs baseline: 1.1728x; 1.0318x over previous
#include <cuda_runtime.h>

// YOLO v0 loss — fused, fully-coalesced, shuffle-masked version.
//
// Channel of a global element e is simply e % 5 (warp base divisible by 5).
// Each lane's float4 overlaps <=2 cells:
//   cellA conf lives in lane L-1's registers (comp (4-c0)&3) -> one rotate
//   SHFL per j-chunk delivers it (sender picks the component: statically
//   known from its own c0). cellB conf (when c0>=2) is inside the lane's
//   own float4. No extra global loads at all -> both streams __ldcs.
// Per-element math in uniform form  w*(o-s)^2 :
//   coord: w=5m, s=t ; conf: m ? (w=1,s=1) : (w=0.5,s=0).

#define LAMBDA_COOR  5.0f
#define LAMBDA_NOOBJ 0.5f

static const int TOTAL_CELLS     = 128 * 256 * 256;          // 8,388,608
static const int BLOCK           = 256;                      // 8 warps
static const int WARPS           = BLOCK / 32;
static const int FLOATS_PER_WARP = 640;                      // 128 cells, %5==0
static const int CELLS_PER_BLOCK = WARPS * 128;              // 1024
static const int GRID            = TOTAL_CELLS / CELLS_PER_BLOCK;  // 8192

__device__ float        g_partials[GRID];
__device__ unsigned int g_done_count = 0;

__device__ __forceinline__ float block_reduce(float acc, float* s_warp) {
#pragma unroll
    for (int off = 16; off > 0; off >>= 1)
        acc += __shfl_down_sync(0xFFFFFFFFu, acc, off);
    int lane = threadIdx.x & 31;
    int wid  = threadIdx.x >> 5;
    if (lane == 0) s_warp[wid] = acc;
    __syncthreads();
    float v = 0.0f;
    if (wid == 0) {
        v = (lane < WARPS) ? s_warp[lane] : 0.0f;
#pragma unroll
        for (int off = 4; off > 0; off >>= 1)
            v += __shfl_down_sync(0xFFFFFFFFu, v, off);
    }
    return v;   // valid in thread 0 only
}

__global__ __launch_bounds__(BLOCK)
void yolo_loss_fused(const float* __restrict__ out, const float* __restrict__ tgt,
                     float* __restrict__ d_loss) {
    const int lane = threadIdx.x & 31;
    const int wid  = threadIdx.x >> 5;

    const size_t warp_gid = (size_t)blockIdx.x * WARPS + wid;
    const size_t base_f   = warp_gid * FLOATS_PER_WARP;      // % 5 == 0

    const float4* o4 = reinterpret_cast<const float4*>(out) + base_f / 4;
    const float4* t4 = reinterpret_cast<const float4*>(tgt) + base_f / 4;

    // ---- 10 fully-coalesced streaming LDG.128, all batched for MLP ----
    float4 ao[5], at[5];
#pragma unroll
    for (int j = 0; j < 5; j++) ao[j] = __ldcs(o4 + j * 32 + lane);
#pragma unroll
    for (int j = 0; j < 5; j++) at[j] = __ldcs(t4 + j * 32 + lane);

    // c0(j) = (4*lane + 128*j) % 5, advanced incrementally (+3 mod 5).
    int c0 = (4 * lane) % 5;

    const unsigned FULL = 0xFFFFFFFFu;
    float acc = 0.0f;
    float rot_prev = 0.0f;   // rot of chunk j-1 (lane-0 wraparound source)

#pragma unroll
    for (int j = 0; j < 5; j++) {
        const float4 a = ao[j];
        const float4 t = at[j];

        // Sender side: component the NEXT lane needs for its cellA conf.
        //   c0==0 -> t.x ; c0==2 -> t.w ; c0==3 -> t.z ; else -> t.y
        float send = (c0 == 0) ? t.x : (c0 == 2) ? t.w : (c0 == 3) ? t.z : t.y;
        float rot  = __shfl_sync(FULL, send, (lane + 31) & 31);

        // cellA conf: own t.x if c0==0, else from lane-1 (lane 0: prev chunk's lane 31).
        float confA = (c0 == 0) ? t.x : (lane != 0 ? rot : rot_prev);
        rot_prev = rot;

        // cellB conf (only meaningful when c0 >= 2): inside own float4.
        float confB = (c0 == 2) ? t.w : (c0 == 3) ? t.z : t.y;

        const bool mA = confA > 0.0f;
        const bool mB = confB > 0.0f;

        // Per-cell weights (uniform w*(o-s)^2 form).
        const float wA5 = mA ? LAMBDA_COOR : 0.0f;
        const float wB5 = mB ? LAMBDA_COOR : 0.0f;
        const bool  mC  = (c0 == 0) ? mA : mB;     // mask of the conf element's cell
        const float wc  = mC ? 1.0f : LAMBDA_NOOBJ;
        const float sc  = mC ? 1.0f : 0.0f;

        const float fo[4] = {a.x, a.y, a.z, a.w};
        const float ft[4] = {t.x, t.y, t.z, t.w};

#pragma unroll
        for (int k = 0; k < 4; k++) {
            // element k is in cellA iff c0 + k < 5; it is the conf element iff
            // c0 == (5-k)%5  (k=0:c0==0, k=1:c0==4, k=2:c0==3, k=3:c0==2).
            const bool isA    = (c0 <= 4 - k);
            const bool isconf = (c0 == ((5 - k) % 5));
            const float w = isconf ? wc : (isA ? wA5 : wB5);
            const float s = isconf ? sc : ft[k];
            const float d = fo[k] - s;
            acc = fmaf(w, d * d, acc);
        }

        c0 += 3; if (c0 >= 5) c0 -= 5;
    }

    __shared__ float s_warp[WARPS];
    __shared__ bool  s_is_last;
    float bsum = block_reduce(acc, s_warp);

    if (threadIdx.x == 0) {
        g_partials[blockIdx.x] = bsum;
        __threadfence();
        unsigned int n = atomicAdd(&g_done_count, 1u);
        s_is_last = (n == (unsigned int)(GRID - 1));
    }
    __syncthreads();

    if (s_is_last) {
        float tsum = 0.0f;
#pragma unroll
        for (int i = threadIdx.x; i < GRID; i += BLOCK)
            tsum += g_partials[i];
        float total = block_reduce(tsum, s_warp);
        if (threadIdx.x == 0) {
            d_loss[0] = total * (1.0f / 128.0f);
            g_done_count = 0;                  // reset for next graph replay
        }
    }
}

extern "C" void kernel_launch(void* const* d_in, const int* in_sizes, int n_in,
                              void* d_out, int out_size) {
    const float* outputs = (const float*)d_in[0];
    const float* targets = (const float*)d_in[1];
    float* loss = (float*)d_out;

    yolo_loss_fused<<<GRID, BLOCK>>>(outputs, targets, loss);
}

// round 6
// speedup vs baseline: 1.2280x; 1.0470x over previous
#include <cuda_runtime.h>

// YOLO v0 loss — fused, coalesced, shuffle-masked; occupancy-push revision.
//
// R5 plateau: DRAM ~74% across 3 different kernels; occ 47% (regs=63,
// 4 blocks/SM). This round: cap regs at 51 via __launch_bounds__(256,5)
// -> 5 blocks/SM (62.5% occ), single-base immediate-offset addressing,
// and merged send/confB selects (-2 SEL per chunk).

#define LAMBDA_COOR  5.0f
#define LAMBDA_NOOBJ 0.5f

static const int TOTAL_CELLS     = 128 * 256 * 256;          // 8,388,608
static const int BLOCK           = 256;                      // 8 warps
static const int WARPS           = BLOCK / 32;
static const int FLOATS_PER_WARP = 640;                      // 128 cells, %5==0
static const int CELLS_PER_BLOCK = WARPS * 128;              // 1024
static const int GRID            = TOTAL_CELLS / CELLS_PER_BLOCK;  // 8192

__device__ float        g_partials[GRID];
__device__ unsigned int g_done_count = 0;

__device__ __forceinline__ float block_reduce(float acc, float* s_warp) {
#pragma unroll
    for (int off = 16; off > 0; off >>= 1)
        acc += __shfl_down_sync(0xFFFFFFFFu, acc, off);
    int lane = threadIdx.x & 31;
    int wid  = threadIdx.x >> 5;
    if (lane == 0) s_warp[wid] = acc;
    __syncthreads();
    float v = 0.0f;
    if (wid == 0) {
        v = (lane < WARPS) ? s_warp[lane] : 0.0f;
#pragma unroll
        for (int off = 4; off > 0; off >>= 1)
            v += __shfl_down_sync(0xFFFFFFFFu, v, off);
    }
    return v;   // valid in thread 0 only
}

__global__ __launch_bounds__(BLOCK, 5)   // cap 51 regs -> 5 blocks/SM (62.5% occ)
void yolo_loss_fused(const float* __restrict__ out, const float* __restrict__ tgt,
                     float* __restrict__ d_loss) {
    const int lane = threadIdx.x & 31;
    const int wid  = threadIdx.x >> 5;

    const size_t warp_gid = (size_t)blockIdx.x * WARPS + wid;
    const size_t base_f   = warp_gid * FLOATS_PER_WARP;      // % 5 == 0

    // Single base per tensor; all 5 accesses use compile-time float4 offsets
    // (j*32) from (base + lane) -> SASS immediate addressing, minimal IMAD.
    const float4* ob = reinterpret_cast<const float4*>(out) + base_f / 4 + lane;
    const float4* tb = reinterpret_cast<const float4*>(tgt) + base_f / 4 + lane;

    // ---- 10 fully-coalesced streaming LDG.128, front-batched for MLP ----
    float4 ao[5], at[5];
#pragma unroll
    for (int j = 0; j < 5; j++) ao[j] = __ldcs(ob + j * 32);
#pragma unroll
    for (int j = 0; j < 5; j++) at[j] = __ldcs(tb + j * 32);

    // c0(j) = (4*lane + 3j) % 5, advanced incrementally.
    int c0 = (4 * lane) % 5;

    const unsigned FULL = 0xFFFFFFFFu;
    float acc = 0.0f;
    float rot_prev = 0.0f;   // lane-0 wraparound source from chunk j-1

#pragma unroll
    for (int j = 0; j < 5; j++) {
        const float4 a = ao[j];
        const float4 t = at[j];

        // confB: conf of the second cell in this float4 (valid when c0>=2).
        // Also doubles as the shuffle payload for c0>=1 (c0==1 needs t.y too).
        const float confB = (c0 == 2) ? t.w : (c0 == 3) ? t.z : t.y;
        const float send  = (c0 == 0) ? t.x : confB;
        const float rot   = __shfl_sync(FULL, send, (lane + 31) & 31);

        // cellA conf: own t.x if c0==0, else lane-1's payload
        // (lane 0 takes chunk j-1's lane-31 payload).
        const float confA = (c0 == 0) ? t.x : (lane != 0 ? rot : rot_prev);
        rot_prev = rot;

        const bool mA = confA > 0.0f;
        const bool mB = confB > 0.0f;

        const float wA5 = mA ? LAMBDA_COOR : 0.0f;
        const float wB5 = mB ? LAMBDA_COOR : 0.0f;
        const bool  mC  = (c0 == 0) ? mA : mB;     // mask of conf element's cell
        const float wc  = mC ? 1.0f : LAMBDA_NOOBJ;
        const float sc  = mC ? 1.0f : 0.0f;

        const float fo[4] = {a.x, a.y, a.z, a.w};
        const float ft[4] = {t.x, t.y, t.z, t.w};

#pragma unroll
        for (int k = 0; k < 4; k++) {
            // element k is in cellA iff c0 + k < 5; conf element iff
            // c0 == (5-k)%5  (k=0:c0==0, k=1:c0==4, k=2:c0==3, k=3:c0==2).
            const bool isA    = (c0 <= 4 - k);
            const bool isconf = (c0 == ((5 - k) % 5));
            const float w = isconf ? wc : (isA ? wA5 : wB5);
            const float s = isconf ? sc : ft[k];
            const float d = fo[k] - s;
            acc = fmaf(w, d * d, acc);
        }

        c0 += 3; if (c0 >= 5) c0 -= 5;
    }

    __shared__ float s_warp[WARPS];
    __shared__ bool  s_is_last;
    float bsum = block_reduce(acc, s_warp);

    if (threadIdx.x == 0) {
        g_partials[blockIdx.x] = bsum;
        __threadfence();
        unsigned int n = atomicAdd(&g_done_count, 1u);
        s_is_last = (n == (unsigned int)(GRID - 1));
    }
    __syncthreads();

    if (s_is_last) {
        float tsum = 0.0f;
#pragma unroll
        for (int i = threadIdx.x; i < GRID; i += BLOCK)
            tsum += g_partials[i];
        float total = block_reduce(tsum, s_warp);
        if (threadIdx.x == 0) {
            d_loss[0] = total * (1.0f / 128.0f);
            g_done_count = 0;                  // reset for next graph replay
        }
    }
}

extern "C" void kernel_launch(void* const* d_in, const int* in_sizes, int n_in,
                              void* d_out, int out_size) {
    const float* outputs = (const float*)d_in[0];
    const float* targets = (const float*)d_in[1];
    float* loss = (float*)d_out;

    yolo_loss_fused<<<GRID, BLOCK>>>(outputs, targets, loss);
}